// round 2
// baseline (speedup 1.0000x reference)
#include <cuda_runtime.h>
#include <mma.h>
#include <math.h>

using namespace nvcuda;

// Problem constants
constexpr int cNB   = 512;
constexpr int cMS   = 8;
constexpr int cT    = 64;
constexpr int cIN   = 360;
constexpr int cH    = 230;
constexpr int cOUT  = 53;
constexpr int cENT  = 8;
constexpr int cB    = cNB * cMS;     // 4096
constexpr int c3H   = 3 * cH;        // 690
constexpr int c2H   = 2 * cH;        // 460
constexpr size_t cTB = (size_t)cT * cB;   // 262144

// ---------------------------------------------------------------------------
// Scratch (static device globals; no allocations allowed)
// ---------------------------------------------------------------------------
static __device__ float g_xg_f[(size_t)cT * cB * c3H];  // [T][B][3H]
static __device__ float g_xg_r[(size_t)cT * cB * c3H];
static __device__ float g_out [(size_t)cT * cB * c2H];  // [T][B][2H] concat(hf,hr)
static __device__ float g_u   [(size_t)cT * cB * c2H];  // word attention tanh(out@Ww+b)
static __device__ float g_h   [2][2][(size_t)cB * cH];  // [dir][pingpong][B*H]
static __device__ float g_score[(size_t)cB * cT];       // [B][T]
static __device__ float g_alpha[(size_t)cB * cT];       // [B][T]
static __device__ float g_wv  [(size_t)cB * c2H];       // word_vec [B][2H]
static __device__ float g_u2  [(size_t)cB * c2H];
static __device__ float g_s2  [cB];
static __device__ float g_sent[(size_t)cNB * c2H];

// ---------------------------------------------------------------------------
// Helpers
// ---------------------------------------------------------------------------
__device__ __forceinline__ float to_tf32(float x) {
    float r;
    asm("cvt.rna.tf32.f32 %0, %1;\n" : "=f"(r) : "f"(x));
    return r;
}
__device__ __forceinline__ float sigmoidf(float x) {
    return 1.f / (1.f + expf(-x));
}

typedef wmma::fragment<wmma::matrix_a, 16, 16, 8, wmma::precision::tf32, wmma::row_major> FragA;
typedef wmma::fragment<wmma::matrix_b, 16, 16, 8, wmma::precision::tf32, wmma::col_major> FragB;
typedef wmma::fragment<wmma::accumulator, 16, 16, 8, float> FragC;

// ---------------------------------------------------------------------------
// Utility kernels
// ---------------------------------------------------------------------------
__global__ void zero_h_kernel() {
    float* p = &g_h[0][0][0];
    size_t n = (size_t)4 * cB * cH;
    size_t stride = (size_t)gridDim.x * blockDim.x;
    for (size_t i = (size_t)blockIdx.x * blockDim.x + threadIdx.x; i < n; i += stride)
        p[i] = 0.f;
}

__global__ void zero_out_kernel(float* p, int n) {
    int i = blockIdx.x * blockDim.x + threadIdx.x;
    if (i < n) p[i] = 0.f;
}

// ---------------------------------------------------------------------------
// Input projection (both directions via blockIdx.z).
// C[M=262144, N=690] = bag[M, K=360] @ W^T + b, remapped rows (b*T+t)->(t*B+b)
// Tile: 128x64, BK=32, TF32 wmma.
// ---------------------------------------------------------------------------
__global__ void __launch_bounds__(256) iproj_kernel(
    const float* __restrict__ bag,
    const float* __restrict__ Wf, const float* __restrict__ bf,
    const float* __restrict__ Wr, const float* __restrict__ br)
{
    const int z = blockIdx.z;
    const float* __restrict__ W    = z ? Wr : Wf;
    const float* __restrict__ bias = z ? br : bf;
    float* __restrict__ dst        = z ? g_xg_r : g_xg_f;

    const int n0 = blockIdx.x * 64;
    const int m0 = blockIdx.y * 128;
    const int tid = threadIdx.x;
    const int wid = tid >> 5;
    const int wm = wid & 3;      // 0..3 (32 rows each)
    const int wn = wid >> 2;     // 0..1 (32 cols each)

    __shared__ __align__(16) float sm[9216];   // 36 KB
    float* As = sm;              // [128][40]
    float* Bs = sm + 5120;       // [64][40]
    float* Cs = sm;              // [128][72] (aliases As/Bs)

    FragC acc[2][2];
    #pragma unroll
    for (int i = 0; i < 2; i++)
        #pragma unroll
        for (int j = 0; j < 2; j++) wmma::fill_fragment(acc[i][j], 0.f);

    for (int k0 = 0; k0 < cIN; k0 += 32) {
        #pragma unroll
        for (int q = 0; q < 16; q++) {
            int idx = q * 256 + tid;
            int r = idx >> 5, k = idx & 31;
            float v = (k0 + k < cIN) ? bag[(size_t)(m0 + r) * cIN + k0 + k] : 0.f;
            As[r * 40 + k] = to_tf32(v);
        }
        #pragma unroll
        for (int q = 0; q < 8; q++) {
            int idx = q * 256 + tid;
            int n = idx >> 5, k = idx & 31;
            float v = 0.f;
            if (n0 + n < c3H && k0 + k < cIN)
                v = W[(size_t)(n0 + n) * cIN + k0 + k];
            Bs[n * 40 + k] = to_tf32(v);
        }
        __syncthreads();
        #pragma unroll
        for (int kk = 0; kk < 32; kk += 8) {
            FragA a0, a1; FragB b0, b1;
            wmma::load_matrix_sync(a0, &As[(wm * 32) * 40 + kk], 40);
            wmma::load_matrix_sync(a1, &As[(wm * 32 + 16) * 40 + kk], 40);
            wmma::load_matrix_sync(b0, &Bs[(wn * 32) * 40 + kk], 40);
            wmma::load_matrix_sync(b1, &Bs[(wn * 32 + 16) * 40 + kk], 40);
            wmma::mma_sync(acc[0][0], a0, b0, acc[0][0]);
            wmma::mma_sync(acc[0][1], a0, b1, acc[0][1]);
            wmma::mma_sync(acc[1][0], a1, b0, acc[1][0]);
            wmma::mma_sync(acc[1][1], a1, b1, acc[1][1]);
        }
        __syncthreads();
    }

    #pragma unroll
    for (int i = 0; i < 2; i++)
        #pragma unroll
        for (int j = 0; j < 2; j++)
            wmma::store_matrix_sync(&Cs[(wm * 32 + i * 16) * 72 + wn * 32 + j * 16],
                                    acc[i][j], 72, wmma::mem_row_major);
    __syncthreads();

    #pragma unroll
    for (int q = 0; q < 32; q++) {
        int idx = q * 256 + tid;
        int r = idx >> 6, c = idx & 63;
        int n = n0 + c;
        if (n < c3H) {
            int m = m0 + r;
            size_t crow = (size_t)(m & (cT - 1)) * cB + (m >> 6);
            dst[crow * c3H + n] = Cs[r * 72 + c] + bias[n];
        }
    }
}

// ---------------------------------------------------------------------------
// Attention GEMM (NN layout, tanh epilogue).
//  SEL 2: C=g_u,  A=g_out (M=T*B), N=K=460
//  SEL 3: C=g_u2, A=g_wv  (M=B),   N=K=460
// ---------------------------------------------------------------------------
template <int SEL>
__global__ void __launch_bounds__(256) attn_gemm_kernel(
    const float* __restrict__ Bw, const float* __restrict__ bias,
    int M, int N, int K)
{
    const float* __restrict__ A = (SEL == 2) ? g_out : g_wv;
    float* __restrict__ C       = (SEL == 2) ? g_u   : g_u2;

    const int n0 = blockIdx.x * 64;
    const int m0 = blockIdx.y * 128;
    const int tid = threadIdx.x;
    const int wid = tid >> 5;
    const int wm = wid & 3;
    const int wn = wid >> 2;

    __shared__ __align__(16) float sm[9216];
    float* As = sm;              // [128][40]
    float* Bs = sm + 5120;       // [64][40]
    float* Cs = sm;              // [128][72]

    FragC acc[2][2];
    #pragma unroll
    for (int i = 0; i < 2; i++)
        #pragma unroll
        for (int j = 0; j < 2; j++) wmma::fill_fragment(acc[i][j], 0.f);

    for (int k0 = 0; k0 < K; k0 += 32) {
        #pragma unroll
        for (int q = 0; q < 16; q++) {
            int idx = q * 256 + tid;
            int r = idx >> 5, k = idx & 31;
            float v = (k0 + k < K) ? A[(size_t)(m0 + r) * K + k0 + k] : 0.f;
            As[r * 40 + k] = to_tf32(v);
        }
        #pragma unroll
        for (int q = 0; q < 8; q++) {
            int idx = q * 256 + tid;
            int kk = idx >> 6, n = idx & 63;      // kk 0..31 over 8 iters
            // iterate kk-major so global reads along n are coalesced
            int kk2 = (q << 2) | (idx >> 6 & 3);  // not used; keep simple below
            (void)kk2;
            float v = 0.f;
            int kidx = (idx >> 6);                // 0..3 within this q? -> recompute
            (void)kidx;
            // simple mapping: idx = kk*64 + n over 2048 elems via two passes
            int lin = q * 256 + tid;
            int kkk = lin >> 6;                   // 0..31
            int nn  = lin & 63;
            if (k0 + kkk < K && n0 + nn < N)
                v = Bw[(size_t)(k0 + kkk) * N + n0 + nn];
            Bs[nn * 40 + kkk] = to_tf32(v);
            (void)kk; (void)n;
        }
        __syncthreads();
        #pragma unroll
        for (int kk = 0; kk < 32; kk += 8) {
            FragA a0, a1; FragB b0, b1;
            wmma::load_matrix_sync(a0, &As[(wm * 32) * 40 + kk], 40);
            wmma::load_matrix_sync(a1, &As[(wm * 32 + 16) * 40 + kk], 40);
            wmma::load_matrix_sync(b0, &Bs[(wn * 32) * 40 + kk], 40);
            wmma::load_matrix_sync(b1, &Bs[(wn * 32 + 16) * 40 + kk], 40);
            wmma::mma_sync(acc[0][0], a0, b0, acc[0][0]);
            wmma::mma_sync(acc[0][1], a0, b1, acc[0][1]);
            wmma::mma_sync(acc[1][0], a1, b0, acc[1][0]);
            wmma::mma_sync(acc[1][1], a1, b1, acc[1][1]);
        }
        __syncthreads();
    }

    #pragma unroll
    for (int i = 0; i < 2; i++)
        #pragma unroll
        for (int j = 0; j < 2; j++)
            wmma::store_matrix_sync(&Cs[(wm * 32 + i * 16) * 72 + wn * 32 + j * 16],
                                    acc[i][j], 72, wmma::mem_row_major);
    __syncthreads();

    #pragma unroll
    for (int q = 0; q < 32; q++) {
        int idx = q * 256 + tid;
        int r = idx >> 6, c = idx & 63;
        int n = n0 + c;
        if (n < N)
            C[(size_t)(m0 + r) * N + n] = tanhf(Cs[r * 72 + c] + bias[n]);
    }
}

// ---------------------------------------------------------------------------
// GRU step, TF32 wmma. One CTA: 128 batch x (3 gates x 32 j) = 128x96 tile.
// All 3 gates land in the same CTA so the nonlinearity fuses on accumulators.
// blockIdx: x = batch tile (32), y = j tile (8), z = dir (2).
// ---------------------------------------------------------------------------
__global__ void __launch_bounds__(256) gru_step_wmma_kernel(
    const float* __restrict__ Whh_f, const float* __restrict__ Whh_r,
    const float* __restrict__ bhh_f, const float* __restrict__ bhh_r,
    int s)
{
    const int dir = blockIdx.z;
    const int t = dir ? (cT - 1 - s) : s;
    const float* __restrict__ xg  = dir ? g_xg_r : g_xg_f;
    const float* __restrict__ Whh = dir ? Whh_r : Whh_f;
    const float* __restrict__ bhh = dir ? bhh_r : bhh_f;
    const float* __restrict__ h_in  = g_h[dir][s & 1];
    float* __restrict__ h_out       = g_h[dir][(s & 1) ^ 1];

    const int b0 = blockIdx.x * 128;
    const int j0 = blockIdx.y * 32;
    const int tid = threadIdx.x;
    const int wid = tid >> 5;
    const int wm = wid & 3;      // batch quadrant (32 rows)
    const int wn = wid >> 2;     // 0..1 -> 48 cols each

    __shared__ __align__(16) float sm[12288];  // 48 KB
    float* Hs = sm;              // [128][40]
    float* Ws = sm + 5120;       // [96][40]
    float* Cs = sm;              // [128][96]

    FragC acc[2][3];
    #pragma unroll
    for (int i = 0; i < 2; i++)
        #pragma unroll
        for (int j = 0; j < 3; j++) wmma::fill_fragment(acc[i][j], 0.f);

    for (int k0 = 0; k0 < cH; k0 += 32) {
        #pragma unroll
        for (int q = 0; q < 16; q++) {
            int idx = q * 256 + tid;
            int r = idx >> 5, k = idx & 31;
            float v = (k0 + k < cH) ? h_in[(size_t)(b0 + r) * cH + k0 + k] : 0.f;
            Hs[r * 40 + k] = to_tf32(v);
        }
        #pragma unroll
        for (int q = 0; q < 12; q++) {
            int idx = q * 256 + tid;
            int c = idx >> 5, k = idx & 31;      // c 0..95
            int g = c >> 5;
            int jc = j0 + (c & 31);
            float v = 0.f;
            if (jc < cH && k0 + k < cH)
                v = Whh[(size_t)(g * cH + jc) * cH + k0 + k];
            Ws[c * 40 + k] = to_tf32(v);
        }
        __syncthreads();
        #pragma unroll
        for (int kk = 0; kk < 32; kk += 8) {
            FragA a0, a1;
            wmma::load_matrix_sync(a0, &Hs[(wm * 32) * 40 + kk], 40);
            wmma::load_matrix_sync(a1, &Hs[(wm * 32 + 16) * 40 + kk], 40);
            #pragma unroll
            for (int j = 0; j < 3; j++) {
                FragB b;
                wmma::load_matrix_sync(b, &Ws[(wn * 48 + j * 16) * 40 + kk], 40);
                wmma::mma_sync(acc[0][j], a0, b, acc[0][j]);
                wmma::mma_sync(acc[1][j], a1, b, acc[1][j]);
            }
        }
        __syncthreads();
    }

    #pragma unroll
    for (int i = 0; i < 2; i++)
        #pragma unroll
        for (int j = 0; j < 3; j++)
            wmma::store_matrix_sync(&Cs[(wm * 32 + i * 16) * 96 + wn * 48 + j * 16],
                                    acc[i][j], 96, wmma::mem_row_major);
    __syncthreads();

    #pragma unroll
    for (int q = 0; q < 16; q++) {
        int idx = q * 256 + tid;
        int bl = idx >> 5, jj = idx & 31;
        int jg = j0 + jj;
        if (jg >= cH) continue;
        int b = b0 + bl;
        const float* xrow = xg + ((size_t)t * cB + b) * c3H;
        float hgr = Cs[bl * 96 + jj];
        float hgz = Cs[bl * 96 + 32 + jj];
        float hgn = Cs[bl * 96 + 64 + jj];
        float r = sigmoidf(xrow[jg]        + hgr + bhh[jg]);
        float z = sigmoidf(xrow[cH + jg]   + hgz + bhh[cH + jg]);
        float n = tanhf(xrow[2 * cH + jg] + r * (hgn + bhh[2 * cH + jg]));
        float hold = h_in[(size_t)b * cH + jg];
        float h2 = (1.f - z) * n + z * hold;
        h_out[(size_t)b * cH + jg] = h2;
        g_out[((size_t)t * cB + b) * c2H + dir * cH + jg] = h2;
    }
}

// ---------------------------------------------------------------------------
// score[row] = u_row . proj   (warp per row)
// ---------------------------------------------------------------------------
template <int SEL2>
__global__ void rowdot_kernel(const float* __restrict__ proj, int M, int N) {
    int row = blockIdx.x * 8 + (threadIdx.x >> 5);
    if (row >= M) return;
    int lane = threadIdx.x & 31;
    const float* __restrict__ U = (SEL2 == 0) ? g_u : g_u2;
    const float* u = U + (size_t)row * N;
    float s = 0.f;
    for (int j = lane; j < N; j += 32) s += u[j] * proj[j];
    #pragma unroll
    for (int o = 16; o; o >>= 1) s += __shfl_xor_sync(0xffffffffu, s, o);
    if (lane == 0) {
        if (SEL2 == 0) {
            int tt = row >> 12;
            int b  = row & (cB - 1);
            g_score[(size_t)b * cT + tt] = s;
        } else {
            g_s2[row] = s;
        }
    }
}

// softmax over T per batch element (warp per b, T=64)
__global__ void softmaxT_kernel() {
    int b = blockIdx.x * 8 + (threadIdx.x >> 5);
    int lane = threadIdx.x & 31;
    const float* s = g_score + (size_t)b * cT;
    float v0 = s[lane], v1 = s[lane + 32];
    float m = fmaxf(v0, v1);
    #pragma unroll
    for (int o = 16; o; o >>= 1) m = fmaxf(m, __shfl_xor_sync(0xffffffffu, m, o));
    float e0 = expf(v0 - m), e1 = expf(v1 - m);
    float sum = e0 + e1;
    #pragma unroll
    for (int o = 16; o; o >>= 1) sum += __shfl_xor_sync(0xffffffffu, sum, o);
    float inv = 1.f / sum;
    g_alpha[(size_t)b * cT + lane] = e0 * inv;
    g_alpha[(size_t)b * cT + lane + 32] = e1 * inv;
}

// word_vec[b][h] = sum_t alpha[b][t] * out[t][b][h]
__global__ void wordvec_kernel() {
    int b = blockIdx.y;
    int h = blockIdx.x * 128 + threadIdx.x;
    if (h >= c2H) return;
    const float* al = g_alpha + (size_t)b * cT;
    float s = 0.f;
    for (int t = 0; t < cT; t++)
        s += al[t] * g_out[((size_t)t * cB + b) * c2H + h];
    g_wv[(size_t)b * c2H + h] = s;
}

// per-doc-bag: beta = softmax over MS of s2; sent_vec = sum_ms beta*wv
__global__ void sentvec_kernel() {
    int nb = blockIdx.x;
    __shared__ float beta[cMS];
    if (threadIdx.x == 0) {
        float v[cMS];
        float m = -1e30f;
        for (int ms = 0; ms < cMS; ms++) { v[ms] = g_s2[nb * cMS + ms]; m = fmaxf(m, v[ms]); }
        float sum = 0.f;
        for (int ms = 0; ms < cMS; ms++) { v[ms] = expf(v[ms] - m); sum += v[ms]; }
        float inv = 1.f / sum;
        for (int ms = 0; ms < cMS; ms++) beta[ms] = v[ms] * inv;
    }
    __syncthreads();
    for (int h = threadIdx.x; h < c2H; h += blockDim.x) {
        float s = 0.f;
        #pragma unroll
        for (int ms = 0; ms < cMS; ms++)
            s += beta[ms] * g_wv[((size_t)nb * cMS + ms) * c2H + h];
        g_sent[(size_t)nb * c2H + h] = s;
    }
}

// fc + scatter into (DOCS, ENT, ENT, OUT)
__global__ void fc_scatter_kernel(const float* __restrict__ fcW,
                                  const float* __restrict__ fcb,
                                  const int* __restrict__ pairs,
                                  float* __restrict__ out)
{
    int nb = blockIdx.x;
    __shared__ float sv[c2H];
    for (int k = threadIdx.x; k < c2H; k += blockDim.x)
        sv[k] = g_sent[(size_t)nb * c2H + k];
    __syncthreads();
    int o = threadIdx.x;
    if (o < cOUT) {
        const float* w = fcW + (size_t)o * c2H;
        float s = fcb[o];
        for (int k = 0; k < c2H; k++) s += sv[k] * w[k];
        int d  = pairs[nb * 3 + 0];
        int e1 = pairs[nb * 3 + 1];
        int e2 = pairs[nb * 3 + 2];
        out[(((size_t)d * cENT + e1) * cENT + e2) * cOUT + o] = s;
    }
}

// ---------------------------------------------------------------------------
extern "C" void kernel_launch(void* const* d_in, const int* in_sizes, int n_in,
                              void* d_out, int out_size) {
    const float* bag   = (const float*)d_in[0];
    const float* Wihf  = (const float*)d_in[1];
    const float* Whhf  = (const float*)d_in[2];
    const float* bihf  = (const float*)d_in[3];
    const float* bhhf  = (const float*)d_in[4];
    const float* Wihr  = (const float*)d_in[5];
    const float* Whhr  = (const float*)d_in[6];
    const float* bihr  = (const float*)d_in[7];
    const float* bhhr  = (const float*)d_in[8];
    const float* Wword = (const float*)d_in[9];
    const float* bword = (const float*)d_in[10];
    const float* pjw   = (const float*)d_in[11];
    const float* Wsent = (const float*)d_in[12];
    const float* bsent = (const float*)d_in[13];
    const float* pjs   = (const float*)d_in[14];
    const float* fcW   = (const float*)d_in[15];
    const float* fcb   = (const float*)d_in[16];
    const int*   pairs = (const int*)d_in[17];
    float* out = (float*)d_out;

    zero_h_kernel<<<2048, 256>>>();
    zero_out_kernel<<<(out_size + 255) / 256, 256>>>(out, out_size);

    // input projections (both dirs in one launch, TF32 tensor cores)
    {
        dim3 grid((c3H + 63) / 64, (int)(cTB / 128), 2);
        iproj_kernel<<<grid, 256>>>(bag, Wihf, bihf, Wihr, bihr);
    }

    // GRU recurrence, 64 steps, both directions per launch
    {
        dim3 grid(cB / 128, (cH + 31) / 32, 2);
        for (int s = 0; s < cT; s++)
            gru_step_wmma_kernel<<<grid, 256>>>(Whhf, Whhr, bhhf, bhhr, s);
    }

    // word attention
    {
        dim3 grid((c2H + 63) / 64, (int)(cTB / 128));
        attn_gemm_kernel<2><<<grid, 256>>>(Wword, bword, (int)cTB, c2H, c2H);
    }
    rowdot_kernel<0><<<(int)(cTB / 8), 256>>>(pjw, (int)cTB, c2H);
    softmaxT_kernel<<<cB / 8, 256>>>();
    {
        dim3 grid((c2H + 127) / 128, cB);
        wordvec_kernel<<<grid, 128>>>();
    }

    // sentence attention
    {
        dim3 grid((c2H + 63) / 64, cB / 128);
        attn_gemm_kernel<3><<<grid, 256>>>(Wsent, bsent, cB, c2H, c2H);
    }
    rowdot_kernel<1><<<cB / 8, 256>>>(pjs, cB, c2H);
    sentvec_kernel<<<cNB, 128>>>();

    // fc + scatter
    fc_scatter_kernel<<<cNB, 64>>>(fcW, fcb, pairs, out);
}

// round 4
// speedup vs baseline: 2.0058x; 2.0058x over previous
#include <cuda_runtime.h>
#include <mma.h>
#include <math.h>
#include <cstdint>

using namespace nvcuda;

// Problem constants
constexpr int cNB   = 512;
constexpr int cMS   = 8;
constexpr int cT    = 64;
constexpr int cIN   = 360;
constexpr int cH    = 230;
constexpr int cHP   = 232;           // padded h stride (16B-aligned rows)
constexpr int cOUT  = 53;
constexpr int cENT  = 8;
constexpr int cB    = cNB * cMS;     // 4096
constexpr int c3H   = 3 * cH;        // 690
constexpr int c2H   = 2 * cH;        // 460
constexpr size_t cTB = (size_t)cT * cB;   // 262144

// ---------------------------------------------------------------------------
// Scratch
// ---------------------------------------------------------------------------
static __device__ float g_xg_f[(size_t)cT * cB * c3H];  // [T][B][3H]
static __device__ float g_xg_r[(size_t)cT * cB * c3H];
static __device__ float g_out [(size_t)cT * cB * c2H];  // [T][B][2H]
static __device__ float g_u   [(size_t)cT * cB * c2H];
static __device__ float g_h   [2][2][(size_t)cB * cHP]; // [dir][pingpong][B*HP]
static __device__ float g_score[(size_t)cB * cT];
static __device__ float g_alpha[(size_t)cB * cT];
static __device__ float g_wv  [(size_t)cB * c2H];
static __device__ float g_u2  [(size_t)cB * c2H];
static __device__ float g_s2  [cB];
static __device__ float g_sent[(size_t)cNB * c2H];

// ---------------------------------------------------------------------------
// Helpers
// ---------------------------------------------------------------------------
__device__ __forceinline__ float to_tf32(float x) {
    float r;
    asm("cvt.rna.tf32.f32 %0, %1;\n" : "=f"(r) : "f"(x));
    return r;
}
__device__ __forceinline__ float sigmoidf(float x) {
    return 1.f / (1.f + expf(-x));
}
__device__ __forceinline__ unsigned int smem_u32(const void* p) {
    return (unsigned int)__cvta_generic_to_shared(p);
}
__device__ __forceinline__ void cp16(unsigned int d, const void* s, int srcsize) {
    asm volatile("cp.async.cg.shared.global [%0], [%1], 16, %2;\n"
                 :: "r"(d), "l"(s), "r"(srcsize));
}
__device__ __forceinline__ void cp8(unsigned int d, const void* s, int srcsize) {
    asm volatile("cp.async.ca.shared.global [%0], [%1], 8, %2;\n"
                 :: "r"(d), "l"(s), "r"(srcsize));
}
__device__ __forceinline__ void cp_commit() {
    asm volatile("cp.async.commit_group;\n");
}
template <int N>
__device__ __forceinline__ void cp_wait() {
    asm volatile("cp.async.wait_group %0;\n" :: "n"(N));
}

typedef wmma::fragment<wmma::matrix_a, 16, 16, 8, wmma::precision::tf32, wmma::row_major> FragA;
typedef wmma::fragment<wmma::matrix_b, 16, 16, 8, wmma::precision::tf32, wmma::col_major> FragBc;
typedef wmma::fragment<wmma::matrix_b, 16, 16, 8, wmma::precision::tf32, wmma::row_major> FragBr;
typedef wmma::fragment<wmma::accumulator, 16, 16, 8, float> FragC;

template <class F>
__device__ __forceinline__ void cvt_frag(F& f) {
    #pragma unroll
    for (int i = 0; i < f.num_elements; i++) f.x[i] = to_tf32(f.x[i]);
}

// ---------------------------------------------------------------------------
// Utility kernels
// ---------------------------------------------------------------------------
__global__ void zero_h_kernel() {
    float* p = &g_h[0][0][0];
    size_t n = (size_t)4 * cB * cHP;
    size_t stride = (size_t)gridDim.x * blockDim.x;
    for (size_t i = (size_t)blockIdx.x * blockDim.x + threadIdx.x; i < n; i += stride)
        p[i] = 0.f;
}
__global__ void zero_out_kernel(float* p, int n) {
    int i = blockIdx.x * blockDim.x + threadIdx.x;
    if (i < n) p[i] = 0.f;
}

// ---------------------------------------------------------------------------
// Input projection: C[M=262144, N=690] = bag @ W^T + b  (TN), row remap.
// 128x64 tile, BK=32, 2-stage cp.async, 8 warps x (32x32).
// ---------------------------------------------------------------------------
__global__ void __launch_bounds__(256, 2) iproj_kernel(
    const float* __restrict__ bag,
    const float* __restrict__ Wf, const float* __restrict__ bf,
    const float* __restrict__ Wr, const float* __restrict__ br)
{
    const int z = blockIdx.z;
    const float* __restrict__ W    = z ? Wr : Wf;
    const float* __restrict__ bias = z ? br : bf;
    float* __restrict__ dst        = z ? g_xg_r : g_xg_f;

    extern __shared__ float sm[];
    float* As = sm;            // [2][128][36]
    float* Bs = sm + 9216;     // [2][64][36]
    float* Cs = sm;            // [128][68]

    const int n0 = blockIdx.x * 64;
    const int m0 = blockIdx.y * 128;
    const int tid = threadIdx.x;
    const int wid = tid >> 5;
    const int wm = wid & 3;    // 32-row tile
    const int wn = wid >> 2;   // 32-col tile

    constexpr int KT = (cIN + 31) / 32;   // 12

    FragC acc[2][2];
    #pragma unroll
    for (int i = 0; i < 2; i++)
        #pragma unroll
        for (int j = 0; j < 2; j++) wmma::fill_fragment(acc[i][j], 0.f);

    auto load_stage = [&](int st, int k0) {
        float* A = As + st * 4608;
        float* B = Bs + st * 2304;
        #pragma unroll
        for (int q = 0; q < 4; q++) {
            int idx = q * 256 + tid;
            int r = idx >> 3, c4 = idx & 7;
            int k = k0 + c4 * 4;
            cp16(smem_u32(&A[r * 36 + c4 * 4]),
                 bag + (size_t)(m0 + r) * cIN + min(k, cIN - 4),
                 (k + 4 <= cIN) ? 16 : 0);
        }
        #pragma unroll
        for (int q = 0; q < 2; q++) {
            int idx = q * 256 + tid;
            int n = idx >> 3, c4 = idx & 7;
            int k = k0 + c4 * 4;
            int nn = min(n0 + n, c3H - 1);
            cp16(smem_u32(&B[n * 36 + c4 * 4]),
                 W + (size_t)nn * cIN + min(k, cIN - 4),
                 (n0 + n < c3H && k + 4 <= cIN) ? 16 : 0);
        }
    };

    load_stage(0, 0);
    cp_commit();

    for (int kt = 0; kt < KT; kt++) {
        if (kt + 1 < KT) {
            load_stage((kt + 1) & 1, (kt + 1) * 32);
            cp_commit();
            cp_wait<1>();
        } else {
            cp_wait<0>();
        }
        __syncthreads();
        float* A = As + (kt & 1) * 4608;
        float* B = Bs + (kt & 1) * 2304;
        #pragma unroll
        for (int kk = 0; kk < 32; kk += 8) {
            FragA a0, a1; FragBc b0, b1;
            wmma::load_matrix_sync(a0, &A[(wm * 32) * 36 + kk], 36);
            wmma::load_matrix_sync(a1, &A[(wm * 32 + 16) * 36 + kk], 36);
            wmma::load_matrix_sync(b0, &B[(wn * 32) * 36 + kk], 36);
            wmma::load_matrix_sync(b1, &B[(wn * 32 + 16) * 36 + kk], 36);
            cvt_frag(a0); cvt_frag(a1); cvt_frag(b0); cvt_frag(b1);
            wmma::mma_sync(acc[0][0], a0, b0, acc[0][0]);
            wmma::mma_sync(acc[0][1], a0, b1, acc[0][1]);
            wmma::mma_sync(acc[1][0], a1, b0, acc[1][0]);
            wmma::mma_sync(acc[1][1], a1, b1, acc[1][1]);
        }
        __syncthreads();
    }

    #pragma unroll
    for (int i = 0; i < 2; i++)
        #pragma unroll
        for (int j = 0; j < 2; j++)
            wmma::store_matrix_sync(&Cs[(wm * 32 + i * 16) * 68 + wn * 32 + j * 16],
                                    acc[i][j], 68, wmma::mem_row_major);
    __syncthreads();

    #pragma unroll
    for (int q = 0; q < 32; q++) {
        int idx = q * 256 + tid;
        int r = idx >> 6, c = idx & 63;
        int n = n0 + c;
        if (n < c3H) {
            int m = m0 + r;
            size_t crow = (size_t)(m & (cT - 1)) * cB + (m >> 6);
            dst[crow * c3H + n] = Cs[r * 68 + c] + bias[n];
        }
    }
}

// ---------------------------------------------------------------------------
// Attention GEMM (NN), tanh epilogue. N=K=460.
//  SEL 2: C=g_u, A=g_out;  SEL 3: C=g_u2, A=g_wv
// ---------------------------------------------------------------------------
template <int SEL>
__global__ void __launch_bounds__(256, 2) attn_gemm_kernel(
    const float* __restrict__ Bw, const float* __restrict__ bias)
{
    const float* __restrict__ A = (SEL == 2) ? g_out : g_wv;
    float* __restrict__ C       = (SEL == 2) ? g_u   : g_u2;
    constexpr int N = c2H, K = c2H;

    extern __shared__ float sm[];
    float* As = sm;            // [2][128][36]
    float* Bs = sm + 9216;     // [2][32][68]  (k-major)
    float* Cs = sm;            // [128][68]

    const int n0 = blockIdx.x * 64;
    const int m0 = blockIdx.y * 128;
    const int tid = threadIdx.x;
    const int wid = tid >> 5;
    const int wm = wid & 3;
    const int wn = wid >> 2;

    constexpr int KT = (K + 31) / 32;   // 15

    FragC acc[2][2];
    #pragma unroll
    for (int i = 0; i < 2; i++)
        #pragma unroll
        for (int j = 0; j < 2; j++) wmma::fill_fragment(acc[i][j], 0.f);

    auto load_stage = [&](int st, int k0) {
        float* Ab = As + st * 4608;
        float* Bb = Bs + st * 2176;
        #pragma unroll
        for (int q = 0; q < 4; q++) {
            int idx = q * 256 + tid;
            int r = idx >> 3, c4 = idx & 7;
            int k = k0 + c4 * 4;
            cp16(smem_u32(&Ab[r * 36 + c4 * 4]),
                 A + (size_t)(m0 + r) * K + min(k, K - 4),
                 (k + 4 <= K) ? 16 : 0);
        }
        #pragma unroll
        for (int q = 0; q < 2; q++) {
            int idx = q * 256 + tid;
            int k = idx >> 4, n4 = idx & 15;
            int kk = k0 + k;
            int n = n0 + n4 * 4;
            cp16(smem_u32(&Bb[k * 68 + n4 * 4]),
                 Bw + (size_t)min(kk, K - 1) * N + min(n, N - 4),
                 (kk < K && n + 4 <= N) ? 16 : 0);
        }
    };

    load_stage(0, 0);
    cp_commit();

    for (int kt = 0; kt < KT; kt++) {
        if (kt + 1 < KT) {
            load_stage((kt + 1) & 1, (kt + 1) * 32);
            cp_commit();
            cp_wait<1>();
        } else {
            cp_wait<0>();
        }
        __syncthreads();
        float* Ab = As + (kt & 1) * 4608;
        float* Bb = Bs + (kt & 1) * 2176;
        #pragma unroll
        for (int kk = 0; kk < 32; kk += 8) {
            FragA a0, a1; FragBr b0, b1;
            wmma::load_matrix_sync(a0, &Ab[(wm * 32) * 36 + kk], 36);
            wmma::load_matrix_sync(a1, &Ab[(wm * 32 + 16) * 36 + kk], 36);
            wmma::load_matrix_sync(b0, &Bb[kk * 68 + wn * 32], 68);
            wmma::load_matrix_sync(b1, &Bb[kk * 68 + wn * 32 + 16], 68);
            cvt_frag(a0); cvt_frag(a1); cvt_frag(b0); cvt_frag(b1);
            wmma::mma_sync(acc[0][0], a0, b0, acc[0][0]);
            wmma::mma_sync(acc[0][1], a0, b1, acc[0][1]);
            wmma::mma_sync(acc[1][0], a1, b0, acc[1][0]);
            wmma::mma_sync(acc[1][1], a1, b1, acc[1][1]);
        }
        __syncthreads();
    }

    #pragma unroll
    for (int i = 0; i < 2; i++)
        #pragma unroll
        for (int j = 0; j < 2; j++)
            wmma::store_matrix_sync(&Cs[(wm * 32 + i * 16) * 68 + wn * 32 + j * 16],
                                    acc[i][j], 68, wmma::mem_row_major);
    __syncthreads();

    #pragma unroll
    for (int q = 0; q < 32; q++) {
        int idx = q * 256 + tid;
        int r = idx >> 6, c = idx & 63;
        int n = n0 + c;
        if (n < N)
            C[(size_t)(m0 + r) * N + n] = tanhf(Cs[r * 68 + c] + bias[n]);
    }
}

// ---------------------------------------------------------------------------
// GRU step: 128 batch x (3 gates x 32 j) tile, 2-stage cp.async, 8 warps x
// (32 x 48). blockIdx: x=batch tile(32), y=j tile(8), z=dir(2).
// ---------------------------------------------------------------------------
__global__ void __launch_bounds__(256, 2) gru_step_kernel(
    const float* __restrict__ Whh_f, const float* __restrict__ Whh_r,
    const float* __restrict__ bhh_f, const float* __restrict__ bhh_r,
    int s)
{
    const int dir = blockIdx.z;
    const int t = dir ? (cT - 1 - s) : s;
    const float* __restrict__ xg  = dir ? g_xg_r : g_xg_f;
    const float* __restrict__ Whh = dir ? Whh_r : Whh_f;
    const float* __restrict__ bhh = dir ? bhh_r : bhh_f;
    const float* __restrict__ h_in  = g_h[dir][s & 1];
    float* __restrict__ h_out       = g_h[dir][(s & 1) ^ 1];

    extern __shared__ float sm[];
    float* Hs = sm;            // [2][128][36]
    float* Ws = sm + 9216;     // [2][96][36]
    float* Cs = sm;            // [128][100]

    const int b0 = blockIdx.x * 128;
    const int j0 = blockIdx.y * 32;
    const int tid = threadIdx.x;
    const int wid = tid >> 5;
    const int wm = wid & 3;    // 32-batch tile
    const int wn = wid >> 2;   // 48-col tile

    constexpr int KT = (cH + 31) / 32;   // 8

    FragC acc[2][3];
    #pragma unroll
    for (int i = 0; i < 2; i++)
        #pragma unroll
        for (int j = 0; j < 3; j++) wmma::fill_fragment(acc[i][j], 0.f);

    auto load_stage = [&](int st, int k0) {
        float* H = Hs + st * 4608;
        float* W = Ws + st * 3456;
        // h tile: rows padded to cHP (16B-aligned)
        #pragma unroll
        for (int q = 0; q < 4; q++) {
            int idx = q * 256 + tid;
            int r = idx >> 3, c4 = idx & 7;
            int k = k0 + c4 * 4;
            int rem = cH - k;
            int sz = rem >= 4 ? 16 : (rem > 0 ? rem * 4 : 0);
            cp16(smem_u32(&H[r * 36 + c4 * 4]),
                 h_in + (size_t)(b0 + r) * cHP + min(k, cHP - 4), sz);
        }
        // weights: 96 rows x 32 k, 8B chunks (row stride 920B is 8B-aligned)
        #pragma unroll
        for (int q = 0; q < 6; q++) {
            int idx = q * 256 + tid;
            int n = idx >> 4, c2 = idx & 15;
            int g = n >> 5;
            int jc = j0 + (n & 31);
            int k = k0 + c2 * 2;
            int jcc = min(jc, cH - 1);
            cp8(smem_u32(&W[n * 36 + c2 * 2]),
                Whh + (size_t)(g * cH + jcc) * cH + min(k, cH - 2),
                (jc < cH && k + 2 <= cH) ? 8 : 0);
        }
    };

    load_stage(0, 0);
    cp_commit();

    for (int kt = 0; kt < KT; kt++) {
        if (kt + 1 < KT) {
            load_stage((kt + 1) & 1, (kt + 1) * 32);
            cp_commit();
            cp_wait<1>();
        } else {
            cp_wait<0>();
        }
        __syncthreads();
        float* H = Hs + (kt & 1) * 4608;
        float* W = Ws + (kt & 1) * 3456;
        #pragma unroll
        for (int kk = 0; kk < 32; kk += 8) {
            FragA a0, a1;
            wmma::load_matrix_sync(a0, &H[(wm * 32) * 36 + kk], 36);
            wmma::load_matrix_sync(a1, &H[(wm * 32 + 16) * 36 + kk], 36);
            cvt_frag(a0); cvt_frag(a1);
            #pragma unroll
            for (int j = 0; j < 3; j++) {
                FragBc b;
                wmma::load_matrix_sync(b, &W[(wn * 48 + j * 16) * 36 + kk], 36);
                cvt_frag(b);
                wmma::mma_sync(acc[0][j], a0, b, acc[0][j]);
                wmma::mma_sync(acc[1][j], a1, b, acc[1][j]);
            }
        }
        __syncthreads();
    }

    #pragma unroll
    for (int i = 0; i < 2; i++)
        #pragma unroll
        for (int j = 0; j < 3; j++)
            wmma::store_matrix_sync(&Cs[(wm * 32 + i * 16) * 100 + wn * 48 + j * 16],
                                    acc[i][j], 100, wmma::mem_row_major);
    __syncthreads();

    #pragma unroll
    for (int q = 0; q < 16; q++) {
        int idx = q * 256 + tid;
        int bl = idx >> 5, jj = idx & 31;
        int jg = j0 + jj;
        if (jg >= cH) continue;
        int b = b0 + bl;
        const float* xrow = xg + ((size_t)t * cB + b) * c3H;
        float hgr = Cs[bl * 100 + jj];
        float hgz = Cs[bl * 100 + 32 + jj];
        float hgn = Cs[bl * 100 + 64 + jj];
        float r = sigmoidf(xrow[jg]        + hgr + bhh[jg]);
        float z = sigmoidf(xrow[cH + jg]   + hgz + bhh[cH + jg]);
        float n = tanhf(xrow[2 * cH + jg] + r * (hgn + bhh[2 * cH + jg]));
        float hold = h_in[(size_t)b * cHP + jg];
        float h2 = (1.f - z) * n + z * hold;
        h_out[(size_t)b * cHP + jg] = h2;
        g_out[((size_t)t * cB + b) * c2H + dir * cH + jg] = h2;
    }
}

// ---------------------------------------------------------------------------
// score reductions / softmax / weighted sums / fc
// ---------------------------------------------------------------------------
template <int SEL2>
__global__ void rowdot_kernel(const float* __restrict__ proj, int M, int N) {
    int row = blockIdx.x * 8 + (threadIdx.x >> 5);
    if (row >= M) return;
    int lane = threadIdx.x & 31;
    const float* __restrict__ U = (SEL2 == 0) ? g_u : g_u2;
    const float* u = U + (size_t)row * N;
    float s = 0.f;
    for (int j = lane; j < N; j += 32) s += u[j] * proj[j];
    #pragma unroll
    for (int o = 16; o; o >>= 1) s += __shfl_xor_sync(0xffffffffu, s, o);
    if (lane == 0) {
        if (SEL2 == 0) {
            int tt = row >> 12;
            int b  = row & (cB - 1);
            g_score[(size_t)b * cT + tt] = s;
        } else {
            g_s2[row] = s;
        }
    }
}

__global__ void softmaxT_kernel() {
    int b = blockIdx.x * 8 + (threadIdx.x >> 5);
    int lane = threadIdx.x & 31;
    const float* s = g_score + (size_t)b * cT;
    float v0 = s[lane], v1 = s[lane + 32];
    float m = fmaxf(v0, v1);
    #pragma unroll
    for (int o = 16; o; o >>= 1) m = fmaxf(m, __shfl_xor_sync(0xffffffffu, m, o));
    float e0 = expf(v0 - m), e1 = expf(v1 - m);
    float sum = e0 + e1;
    #pragma unroll
    for (int o = 16; o; o >>= 1) sum += __shfl_xor_sync(0xffffffffu, sum, o);
    float inv = 1.f / sum;
    g_alpha[(size_t)b * cT + lane] = e0 * inv;
    g_alpha[(size_t)b * cT + lane + 32] = e1 * inv;
}

__global__ void wordvec_kernel() {
    int b = blockIdx.y;
    int h = blockIdx.x * 128 + threadIdx.x;
    if (h >= c2H) return;
    const float* al = g_alpha + (size_t)b * cT;
    float s = 0.f;
    for (int t = 0; t < cT; t++)
        s += al[t] * g_out[((size_t)t * cB + b) * c2H + h];
    g_wv[(size_t)b * c2H + h] = s;
}

__global__ void sentvec_kernel() {
    int nb = blockIdx.x;
    __shared__ float beta[cMS];
    if (threadIdx.x == 0) {
        float v[cMS];
        float m = -1e30f;
        for (int ms = 0; ms < cMS; ms++) { v[ms] = g_s2[nb * cMS + ms]; m = fmaxf(m, v[ms]); }
        float sum = 0.f;
        for (int ms = 0; ms < cMS; ms++) { v[ms] = expf(v[ms] - m); sum += v[ms]; }
        float inv = 1.f / sum;
        for (int ms = 0; ms < cMS; ms++) beta[ms] = v[ms] * inv;
    }
    __syncthreads();
    for (int h = threadIdx.x; h < c2H; h += blockDim.x) {
        float s = 0.f;
        #pragma unroll
        for (int ms = 0; ms < cMS; ms++)
            s += beta[ms] * g_wv[((size_t)nb * cMS + ms) * c2H + h];
        g_sent[(size_t)nb * c2H + h] = s;
    }
}

__global__ void fc_scatter_kernel(const float* __restrict__ fcW,
                                  const float* __restrict__ fcb,
                                  const int* __restrict__ pairs,
                                  float* __restrict__ out)
{
    int nb = blockIdx.x;
    __shared__ float sv[c2H];
    for (int k = threadIdx.x; k < c2H; k += blockDim.x)
        sv[k] = g_sent[(size_t)nb * c2H + k];
    __syncthreads();
    int o = threadIdx.x;
    if (o < cOUT) {
        const float* w = fcW + (size_t)o * c2H;
        float s = fcb[o];
        for (int k = 0; k < c2H; k++) s += sv[k] * w[k];
        int d  = pairs[nb * 3 + 0];
        int e1 = pairs[nb * 3 + 1];
        int e2 = pairs[nb * 3 + 2];
        out[(((size_t)d * cENT + e1) * cENT + e2) * cOUT + o] = s;
    }
}

// ---------------------------------------------------------------------------
extern "C" void kernel_launch(void* const* d_in, const int* in_sizes, int n_in,
                              void* d_out, int out_size) {
    const float* bag   = (const float*)d_in[0];
    const float* Wihf  = (const float*)d_in[1];
    const float* Whhf  = (const float*)d_in[2];
    const float* bihf  = (const float*)d_in[3];
    const float* bhhf  = (const float*)d_in[4];
    const float* Wihr  = (const float*)d_in[5];
    const float* Whhr  = (const float*)d_in[6];
    const float* bihr  = (const float*)d_in[7];
    const float* bhhr  = (const float*)d_in[8];
    const float* Wword = (const float*)d_in[9];
    const float* bword = (const float*)d_in[10];
    const float* pjw   = (const float*)d_in[11];
    const float* Wsent = (const float*)d_in[12];
    const float* bsent = (const float*)d_in[13];
    const float* pjs   = (const float*)d_in[14];
    const float* fcW   = (const float*)d_in[15];
    const float* fcb   = (const float*)d_in[16];
    const int*   pairs = (const int*)d_in[17];
    float* out = (float*)d_out;

    constexpr int smem_iproj = (2 * 128 * 36 + 2 * 64 * 36) * 4;   // 55296
    constexpr int smem_attn  = (2 * 128 * 36 + 2 * 32 * 68) * 4;   // 54272
    constexpr int smem_gru   = (2 * 128 * 36 + 2 * 96 * 36) * 4;   // 64512

    static int attr_done = 0;
    if (!attr_done) {
        cudaFuncSetAttribute(iproj_kernel, cudaFuncAttributeMaxDynamicSharedMemorySize, smem_iproj);
        cudaFuncSetAttribute(attn_gemm_kernel<2>, cudaFuncAttributeMaxDynamicSharedMemorySize, smem_attn);
        cudaFuncSetAttribute(attn_gemm_kernel<3>, cudaFuncAttributeMaxDynamicSharedMemorySize, smem_attn);
        cudaFuncSetAttribute(gru_step_kernel, cudaFuncAttributeMaxDynamicSharedMemorySize, smem_gru);
        attr_done = 1;
    }

    zero_h_kernel<<<2048, 256>>>();
    zero_out_kernel<<<(out_size + 255) / 256, 256>>>(out, out_size);

    // input projections (both dirs)
    {
        dim3 grid((c3H + 63) / 64, (int)(cTB / 128), 2);
        iproj_kernel<<<grid, 256, smem_iproj>>>(bag, Wihf, bihf, Wihr, bihr);
    }

    // GRU recurrence
    {
        dim3 grid(cB / 128, (cH + 31) / 32, 2);
        for (int s = 0; s < cT; s++)
            gru_step_kernel<<<grid, 256, smem_gru>>>(Whhf, Whhr, bhhf, bhhr, s);
    }

    // word attention
    {
        dim3 grid((c2H + 63) / 64, (int)(cTB / 128));
        attn_gemm_kernel<2><<<grid, 256, smem_attn>>>(Wword, bword);
    }
    rowdot_kernel<0><<<(int)(cTB / 8), 256>>>(pjw, (int)cTB, c2H);
    softmaxT_kernel<<<cB / 8, 256>>>();
    {
        dim3 grid((c2H + 127) / 128, cB);
        wordvec_kernel<<<grid, 128>>>();
    }

    // sentence attention
    {
        dim3 grid((c2H + 63) / 64, cB / 128);
        attn_gemm_kernel<3><<<grid, 256, smem_attn>>>(Wsent, bsent);
    }
    rowdot_kernel<1><<<cB / 8, 256>>>(pjs, cB, c2H);
    sentvec_kernel<<<cNB, 128>>>();

    fc_scatter_kernel<<<cNB, 64>>>(fcW, fcb, pairs, out);
}